// round 8
// baseline (speedup 1.0000x reference)
// R8: ldmatrix.x4 fragments (4x fewer issue slots, same validated layout)
//     + 3-stage cp.async pipeline (2 groups in flight, hide DRAM latency)
#include <cuda_runtime.h>
#include <cstdint>

#define T_TOK 1024
#define H_DIM 1024
#define NE 32
#define TOPK 4
#define F_DIM 1024
#define TWO_F 2048
#define LIMIT 7.0f
#define ALPHA 1.702f
#define EPS 1e-5f

#define BM 128
#define BN 128
#define BK 16
#define LDA (BK + 4)   // 20-float row stride: 16B aligned, ldmatrix conflict-free
#define NSTAGE 3

// ------------------- scratch -------------------
__device__ float g_tnorm[T_TOK * H_DIM];
__device__ int   g_counts[NE];
__device__ int   g_bases[NE];
__device__ int   g_expert_ids[T_TOK * TOPK];
__device__ float g_weights[T_TOK * TOPK];
__device__ int   g_slot_token[T_TOK * TOPK];
__device__ float g_slot_weight[T_TOK * TOPK];
__device__ int   g_token_slot[T_TOK * TOPK];
__device__ float g_act[(size_t)T_TOK * TOPK * F_DIM];
__device__ float g_y[(size_t)T_TOK * TOPK * H_DIM];

// ------------------- helpers -------------------
__device__ __forceinline__ void mma_tf32(float (&d)[4], const uint32_t (&a)[4],
                                         const uint32_t (&b)[2]) {
    asm volatile(
        "mma.sync.aligned.m16n8k8.row.col.f32.tf32.tf32.f32 "
        "{%0,%1,%2,%3}, {%4,%5,%6,%7}, {%8,%9}, {%0,%1,%2,%3};\n"
        : "+f"(d[0]), "+f"(d[1]), "+f"(d[2]), "+f"(d[3])
        : "r"(a[0]), "r"(a[1]), "r"(a[2]), "r"(a[3]), "r"(b[0]), "r"(b[1]));
}

__device__ __forceinline__ void ldsm4(uint32_t& r0, uint32_t& r1, uint32_t& r2,
                                      uint32_t& r3, uint32_t addr) {
    asm volatile("ldmatrix.sync.aligned.m8n8.x4.shared.b16 {%0,%1,%2,%3}, [%4];"
                 : "=r"(r0), "=r"(r1), "=r"(r2), "=r"(r3) : "r"(addr));
}

__device__ __forceinline__ void cp16(uint32_t dst, const float* src, uint32_t sz) {
    asm volatile("cp.async.ca.shared.global [%0], [%1], 16, %2;\n"
                 ::"r"(dst), "l"(src), "r"(sz));
}
__device__ __forceinline__ void cp_commit() { asm volatile("cp.async.commit_group;\n"); }
template <int N>
__device__ __forceinline__ void cp_wait() {
    asm volatile("cp.async.wait_group %0;\n" ::"n"(N));
}

// ------------------- kernel 0: reset counts -------------------
__global__ void k_zero() {
    if (threadIdx.x < NE) g_counts[threadIdx.x] = 0;
}

// ------------------- kernel 1: rmsnorm + gate + top4 + softmax ----------------
__global__ void k_gate(const float* __restrict__ x, const float* __restrict__ scale,
                       const float* __restrict__ gw, const float* __restrict__ gb) {
    int t = blockIdx.x;
    int tid = threadIdx.x;
    __shared__ float sh[H_DIM];
    __shared__ float red[8];
    __shared__ float logits[NE];
    const float* xr = x + (size_t)t * H_DIM;

    float ss = 0.f;
    for (int i = tid; i < H_DIM; i += 256) { float v = xr[i]; ss += v * v; }
    for (int o = 16; o; o >>= 1) ss += __shfl_xor_sync(~0u, ss, o);
    int warp = tid >> 5, lane = tid & 31;
    if (!lane) red[warp] = ss;
    __syncthreads();
    if (tid < 8) {
        float s = red[tid];
        for (int o = 4; o; o >>= 1) s += __shfl_xor_sync(0xffu, s, o);
        if (!tid) red[0] = s;
    }
    __syncthreads();
    float inv = rsqrtf(red[0] * (1.0f / H_DIM) + EPS);
    for (int i = tid; i < H_DIM; i += 256) {
        float v = xr[i] * inv * scale[i];
        sh[i] = v;
        g_tnorm[(size_t)t * H_DIM + i] = v;
    }
    __syncthreads();
    for (int e = warp; e < NE; e += 8) {
        const float* w = gw + (size_t)e * H_DIM;
        float s = 0.f;
        for (int i = lane; i < H_DIM; i += 32) s += sh[i] * w[i];
        for (int o = 16; o; o >>= 1) s += __shfl_xor_sync(~0u, s, o);
        if (!lane) logits[e] = s + gb[e];
    }
    __syncthreads();
    if (tid == 0) {
        unsigned used = 0;
        float v[TOPK]; int ix[TOPK];
        for (int k = 0; k < TOPK; k++) {
            float best = -3.4e38f; int bi = 0;
            for (int e2 = 0; e2 < NE; e2++)
                if (!((used >> e2) & 1u) && logits[e2] > best) { best = logits[e2]; bi = e2; }
            used |= 1u << bi; v[k] = best; ix[k] = bi;
        }
        float mx = v[0], sum = 0.f, w4[TOPK];
        for (int k = 0; k < TOPK; k++) { w4[k] = __expf(v[k] - mx); sum += w4[k]; }
        float rs = 1.f / sum;
        for (int k = 0; k < TOPK; k++) {
            g_expert_ids[t * TOPK + k] = ix[k];
            g_weights[t * TOPK + k] = w4[k] * rs;
            atomicAdd(&g_counts[ix[k]], 1);
        }
    }
}

// ------------------- kernel 2: deterministic scatter --------------------------
__global__ void k_scatter() {
    int e = threadIdx.x >> 5;
    int lane = threadIdx.x & 31;
    int base = 0;
    for (int i = 0; i < e; i++) base += g_counts[i];
    if (!lane) g_bases[e] = base;
    int running = 0;
    for (int j0 = 0; j0 < T_TOK * TOPK; j0 += 32) {
        int j = j0 + lane;
        int ee = g_expert_ids[j];
        unsigned m = __ballot_sync(~0u, ee == e);
        if (ee == e) {
            int slot = base + running + __popc(m & ((1u << lane) - 1u));
            g_slot_token[slot] = j >> 2;
            g_slot_weight[slot] = g_weights[j];
            g_token_slot[j] = slot;
        }
        running += __popc(m);
    }
}

// ------------------- kernel 3/4: tf32 tensor GEMM, ldmatrix + 3-stage ---------
template <int IS_G1>
__global__ __launch_bounds__(256, 2) void k_gemm(const float* __restrict__ W,
                                                 const float* __restrict__ bias) {
    const int Kd = 1024;
    const int Nd = IS_G1 ? TWO_F : H_DIM;
    const int e = blockIdx.z;
    const int cnt = g_counts[e];
    const int m0 = blockIdx.y * BM;
    if (m0 >= cnt) return;
    const int base = g_bases[e];
    const int n0 = blockIdx.x * BN;

    __shared__ float As[NSTAGE][BM][LDA];
    __shared__ float Bs[NSTAGE][BN][LDA];
    const uint32_t SZA = BM * LDA * 4;
    const uint32_t SZB = BN * LDA * 4;

    const int tid = threadIdx.x;
    const int warp = tid >> 5, lane = tid & 31;
    const int g = lane >> 2, tg = lane & 3;
    const int wm = (warp & 1) * 64;
    const int wn = (warp >> 1) * 32;

    // ---- loader mapping ----
    const int lr = tid >> 2;
    const int lk = (tid & 3) * 4;
    const float* Wb = W + (size_t)e * Nd * Kd;

    const float* a0 = Wb; uint32_t sz0 = 0;
    const float* a1 = Wb; uint32_t sz1 = 0;
    if (m0 + lr < cnt) {
        int s = base + m0 + lr;
        a0 = (IS_G1 ? (g_tnorm + (size_t)g_slot_token[s] * H_DIM)
                    : (g_act + (size_t)s * F_DIM)) + lk;
        sz0 = 16;
    }
    if (m0 + lr + 64 < cnt) {
        int s = base + m0 + lr + 64;
        a1 = (IS_G1 ? (g_tnorm + (size_t)g_slot_token[s] * H_DIM)
                    : (g_act + (size_t)s * F_DIM)) + lk;
        sz1 = 16;
    }
    const float* b0 = Wb + (size_t)(n0 + lr) * Kd + lk;
    const float* b1 = Wb + (size_t)(n0 + lr + 64) * Kd + lk;

    uint32_t sA0 = (uint32_t)__cvta_generic_to_shared(&As[0][lr][lk]);
    uint32_t sA1 = (uint32_t)__cvta_generic_to_shared(&As[0][lr + 64][lk]);
    uint32_t sB0 = (uint32_t)__cvta_generic_to_shared(&Bs[0][lr][lk]);
    uint32_t sB1 = (uint32_t)__cvta_generic_to_shared(&Bs[0][lr + 64][lk]);

    // ---- ldmatrix per-lane addresses ----
    // A: quad q=lane>>3, r=lane&7: row_off=(q&1)*8+r, k_off=(q>>1)*4
    // regs {0,1,2,3} -> a0(rows0-7,k0-3), a1(rows8-15,k0-3), a2(rows0-7,k4-7), a3(rows8-15,k4-7)
    const int q = lane >> 3, qr = lane & 7;
    uint32_t aFragBase = (uint32_t)__cvta_generic_to_shared(
        &As[0][wm + (q & 1) * 8 + qr][(q >> 1) * 4]);
    // B: regs {0,1,2,3} -> b[ni][0], b[ni][1], b[ni+1][0], b[ni+1][1]
    //    n_off=(q>>1)*8+r, k_off=(q&1)*4
    uint32_t bFragBase = (uint32_t)__cvta_generic_to_shared(
        &Bs[0][wn + (q >> 1) * 8 + qr][(q & 1) * 4]);

    float acc[4][4][4];
#pragma unroll
    for (int mi = 0; mi < 4; mi++)
#pragma unroll
        for (int ni = 0; ni < 4; ni++)
#pragma unroll
            for (int z = 0; z < 4; z++) acc[mi][ni][z] = 0.f;

    const int NIT = Kd / BK;  // 64
    // prologue: stages 0,1
#pragma unroll
    for (int p = 0; p < 2; p++) {
        int k0 = p * BK;
        cp16(sA0 + p * SZA, a0 + k0, sz0);
        cp16(sA1 + p * SZA, a1 + k0, sz1);
        cp16(sB0 + p * SZB, b0 + k0, 16);
        cp16(sB1 + p * SZB, b1 + k0, 16);
        cp_commit();
    }

#pragma unroll 1
    for (int it = 0; it < NIT; it++) {
        if (it < NIT - 1) cp_wait<1>(); else cp_wait<0>();
        __syncthreads();
        if (it + 2 < NIT) {
            int k0 = (it + 2) * BK;
            uint32_t so = (uint32_t)((it + 2) % NSTAGE);
            cp16(sA0 + so * SZA, a0 + k0, sz0);
            cp16(sA1 + so * SZA, a1 + k0, sz1);
            cp16(sB0 + so * SZB, b0 + k0, 16);
            cp16(sB1 + so * SZB, b1 + k0, 16);
            cp_commit();
        }
        const uint32_t s = (uint32_t)(it % NSTAGE);
        const uint32_t aS = aFragBase + s * SZA;
        const uint32_t bS = bFragBase + s * SZB;
#pragma unroll
        for (int kk = 0; kk < BK; kk += 8) {
            uint32_t a[4][4], b[2][4];
#pragma unroll
            for (int mi = 0; mi < 4; mi++)
                ldsm4(a[mi][0], a[mi][1], a[mi][2], a[mi][3],
                      aS + (uint32_t)((mi * 16 * LDA + kk) * 4));
#pragma unroll
            for (int p = 0; p < 2; p++)
                ldsm4(b[p][0], b[p][1], b[p][2], b[p][3],
                      bS + (uint32_t)((p * 16 * LDA + kk) * 4));
#pragma unroll
            for (int mi = 0; mi < 4; mi++) {
#pragma unroll
                for (int p = 0; p < 2; p++) {
                    const uint32_t bf0[2] = {b[p][0], b[p][1]};
                    const uint32_t bf1[2] = {b[p][2], b[p][3]};
                    mma_tf32(acc[mi][2 * p + 0], a[mi], bf0);
                    mma_tf32(acc[mi][2 * p + 1], a[mi], bf1);
                }
            }
        }
        __syncthreads();
    }

    // ---- epilogue ----
#pragma unroll
    for (int mi = 0; mi < 4; mi++) {
#pragma unroll
        for (int h2 = 0; h2 < 2; h2++) {
            int r = m0 + wm + mi * 16 + g + h2 * 8;
            if (r >= cnt) continue;
            int slot = base + r;
            float wsl = IS_G1 ? g_slot_weight[slot] : 0.f;
#pragma unroll
            for (int ni = 0; ni < 4; ni++) {
                int ceven = n0 + wn + ni * 8 + 2 * tg;
                float v0 = acc[mi][ni][h2 * 2 + 0];
                float v1 = acc[mi][ni][h2 * 2 + 1];
                if (IS_G1) {
                    const float2 bb = *(const float2*)(bias + (size_t)e * TWO_F + ceven);
                    float glu = fminf(v0 + bb.x, LIMIT);
                    float lin = fminf(fmaxf(v1 + bb.y, -LIMIT), LIMIT);
                    float act = glu * (1.f / (1.f + __expf(-ALPHA * glu))) * (lin + 1.f);
                    g_act[(size_t)slot * F_DIM + (ceven >> 1)] = wsl * act;
                } else {
                    *(float2*)(g_y + (size_t)slot * H_DIM + ceven) = make_float2(v0, v1);
                }
            }
        }
    }
}

// ------------------- kernel 5: combine + residual + b2 -------------------
__global__ void k_combine(const float* __restrict__ x, const float* __restrict__ b2,
                          float* __restrict__ out) {
    int t = blockIdx.x, tid = threadIdx.x;
    int s0 = g_token_slot[t * 4 + 0], s1 = g_token_slot[t * 4 + 1];
    int s2 = g_token_slot[t * 4 + 2], s3 = g_token_slot[t * 4 + 3];
    int e0 = g_expert_ids[t * 4 + 0], e1 = g_expert_ids[t * 4 + 1];
    int e2 = g_expert_ids[t * 4 + 2], e3 = g_expert_ids[t * 4 + 3];
    float w0 = g_weights[t * 4 + 0], w1v = g_weights[t * 4 + 1];
    float w2v = g_weights[t * 4 + 2], w3 = g_weights[t * 4 + 3];
    for (int i = tid; i < H_DIM; i += 256) {
        float v = x[(size_t)t * H_DIM + i];
        v += g_y[(size_t)s0 * H_DIM + i] + w0 * b2[(size_t)e0 * H_DIM + i];
        v += g_y[(size_t)s1 * H_DIM + i] + w1v * b2[(size_t)e1 * H_DIM + i];
        v += g_y[(size_t)s2 * H_DIM + i] + w2v * b2[(size_t)e2 * H_DIM + i];
        v += g_y[(size_t)s3 * H_DIM + i] + w3 * b2[(size_t)e3 * H_DIM + i];
        out[(size_t)t * H_DIM + i] = v;
    }
}

// ------------------- launcher -------------------
extern "C" void kernel_launch(void* const* d_in, const int* in_sizes, int n_in,
                              void* d_out, int out_size) {
    const float* x = (const float*)d_in[0];
    const float* norm_scale = (const float*)d_in[1];
    const float* gate_w = (const float*)d_in[2];
    const float* gate_b = (const float*)d_in[3];
    const float* w1 = (const float*)d_in[4];
    const float* b1 = (const float*)d_in[5];
    const float* w2 = (const float*)d_in[6];
    const float* b2 = (const float*)d_in[7];
    float* out = (float*)d_out;

    k_zero<<<1, 32>>>();
    k_gate<<<T_TOK, 256>>>(x, norm_scale, gate_w, gate_b);
    k_scatter<<<1, 1024>>>();
    dim3 grid1(TWO_F / BN, T_TOK / BM, NE);
    k_gemm<1><<<grid1, 256>>>(w1, b1);
    dim3 grid2(H_DIM / BN, T_TOK / BM, NE);
    k_gemm<0><<<grid2, 256>>>(w2, nullptr);
    k_combine<<<T_TOK, 256>>>(x, b2, out);
}

// round 10
// speedup vs baseline: 1.5197x; 1.5197x over previous
// R9: bf16 operands + mma.m16n8k16 — halve smem crossbar bytes (the measured
// binding resource) AND double tensor work per instruction. tnorm/act stored
// bf16 (A loads convert-free); weights converted in-register. Reg-staged
// single-stage smem pipeline (no cp.async), 12.3KB smem, ~115 regs, no spills.
#include <cuda_runtime.h>
#include <cuda_bf16.h>
#include <cstdint>

#define T_TOK 1024
#define H_DIM 1024
#define NE 32
#define TOPK 4
#define F_DIM 1024
#define TWO_F 2048
#define LIMIT 7.0f
#define ALPHA 1.702f
#define EPS 1e-5f

#define BM 128
#define BN 128
#define BK 16
#define LDH 24   // bf16 elems per smem row: 16 data + 8 pad = 48B (bank-permuting)

// ------------------- scratch -------------------
__device__ __nv_bfloat16 g_tnorm_h[T_TOK * H_DIM];                 // 2 MB
__device__ int   g_counts[NE];
__device__ int   g_bases[NE];
__device__ int   g_expert_ids[T_TOK * TOPK];
__device__ float g_weights[T_TOK * TOPK];
__device__ int   g_slot_token[T_TOK * TOPK];
__device__ float g_slot_weight[T_TOK * TOPK];
__device__ int   g_token_slot[T_TOK * TOPK];
__device__ __nv_bfloat16 g_act_h[(size_t)T_TOK * TOPK * F_DIM];    // 8 MB
__device__ float g_y[(size_t)T_TOK * TOPK * H_DIM];                // 16 MB

// ------------------- helpers -------------------
__device__ __forceinline__ void mma_bf16(float (&d)[4], const uint32_t (&a)[4],
                                         uint32_t b0, uint32_t b1) {
    asm volatile(
        "mma.sync.aligned.m16n8k16.row.col.f32.bf16.bf16.f32 "
        "{%0,%1,%2,%3}, {%4,%5,%6,%7}, {%8,%9}, {%0,%1,%2,%3};\n"
        : "+f"(d[0]), "+f"(d[1]), "+f"(d[2]), "+f"(d[3])
        : "r"(a[0]), "r"(a[1]), "r"(a[2]), "r"(a[3]), "r"(b0), "r"(b1));
}

__device__ __forceinline__ void ldsm4(uint32_t (&r)[4], uint32_t addr) {
    asm volatile("ldmatrix.sync.aligned.m8n8.x4.shared.b16 {%0,%1,%2,%3}, [%4];"
                 : "=r"(r[0]), "=r"(r[1]), "=r"(r[2]), "=r"(r[3]) : "r"(addr));
}

// pack two fp32 -> bf16x2 word, lo = first arg (lower k index)
__device__ __forceinline__ uint32_t packbf(float lo, float hi) {
    uint32_t r;
    asm("cvt.rn.bf16x2.f32 %0, %1, %2;" : "=r"(r) : "f"(hi), "f"(lo));
    return r;
}

// ------------------- kernel 0: reset counts -------------------
__global__ void k_zero() {
    if (threadIdx.x < NE) g_counts[threadIdx.x] = 0;
}

// ------------------- kernel 1: rmsnorm + gate + top4 + softmax ----------------
__global__ void k_gate(const float* __restrict__ x, const float* __restrict__ scale,
                       const float* __restrict__ gw, const float* __restrict__ gb) {
    int t = blockIdx.x;
    int tid = threadIdx.x;
    __shared__ float sh[H_DIM];
    __shared__ float red[8];
    __shared__ float logits[NE];
    const float* xr = x + (size_t)t * H_DIM;

    float ss = 0.f;
    for (int i = tid; i < H_DIM; i += 256) { float v = xr[i]; ss += v * v; }
    for (int o = 16; o; o >>= 1) ss += __shfl_xor_sync(~0u, ss, o);
    int warp = tid >> 5, lane = tid & 31;
    if (!lane) red[warp] = ss;
    __syncthreads();
    if (tid < 8) {
        float s = red[tid];
        for (int o = 4; o; o >>= 1) s += __shfl_xor_sync(0xffu, s, o);
        if (!tid) red[0] = s;
    }
    __syncthreads();
    float inv = rsqrtf(red[0] * (1.0f / H_DIM) + EPS);
    for (int i = tid; i < H_DIM; i += 256) {
        float v = xr[i] * inv * scale[i];
        sh[i] = v;
        g_tnorm_h[(size_t)t * H_DIM + i] = __float2bfloat16_rn(v);
    }
    __syncthreads();
    for (int e = warp; e < NE; e += 8) {
        const float* w = gw + (size_t)e * H_DIM;
        float s = 0.f;
        for (int i = lane; i < H_DIM; i += 32) s += sh[i] * w[i];
        for (int o = 16; o; o >>= 1) s += __shfl_xor_sync(~0u, s, o);
        if (!lane) logits[e] = s + gb[e];
    }
    __syncthreads();
    if (tid == 0) {
        unsigned used = 0;
        float v[TOPK]; int ix[TOPK];
        for (int k = 0; k < TOPK; k++) {
            float best = -3.4e38f; int bi = 0;
            for (int e2 = 0; e2 < NE; e2++)
                if (!((used >> e2) & 1u) && logits[e2] > best) { best = logits[e2]; bi = e2; }
            used |= 1u << bi; v[k] = best; ix[k] = bi;
        }
        float mx = v[0], sum = 0.f, w4[TOPK];
        for (int k = 0; k < TOPK; k++) { w4[k] = __expf(v[k] - mx); sum += w4[k]; }
        float rs = 1.f / sum;
        for (int k = 0; k < TOPK; k++) {
            g_expert_ids[t * TOPK + k] = ix[k];
            g_weights[t * TOPK + k] = w4[k] * rs;
            atomicAdd(&g_counts[ix[k]], 1);
        }
    }
}

// ------------------- kernel 2: deterministic scatter --------------------------
__global__ void k_scatter() {
    int e = threadIdx.x >> 5;
    int lane = threadIdx.x & 31;
    int base = 0;
    for (int i = 0; i < e; i++) base += g_counts[i];
    if (!lane) g_bases[e] = base;
    int running = 0;
    for (int j0 = 0; j0 < T_TOK * TOPK; j0 += 32) {
        int j = j0 + lane;
        int ee = g_expert_ids[j];
        unsigned m = __ballot_sync(~0u, ee == e);
        if (ee == e) {
            int slot = base + running + __popc(m & ((1u << lane) - 1u));
            g_slot_token[slot] = j >> 2;
            g_slot_weight[slot] = g_weights[j];
            g_token_slot[j] = slot;
        }
        running += __popc(m);
    }
}

// ------------------- kernel 3/4: bf16 tensor GEMM -----------------------------
// IS_G1=1: act_h[slot,f] = bf16(w_slot * swiglu(tnorm_h[token] @ w1[e]^T + b1[e]))
// IS_G1=0: y[slot,h]     = act_h[slot,:] @ w2[e]^T
template <int IS_G1>
__global__ __launch_bounds__(256, 2) void k_gemm(const float* __restrict__ W,
                                                 const float* __restrict__ bias) {
    const int Kd = 1024;
    const int Nd = IS_G1 ? TWO_F : H_DIM;
    const int e = blockIdx.z;
    const int cnt = g_counts[e];
    const int m0 = blockIdx.y * BM;
    if (m0 >= cnt) return;
    const int base = g_bases[e];
    const int n0 = blockIdx.x * BN;

    __shared__ __align__(16) __nv_bfloat16 As[BM * LDH];
    __shared__ __align__(16) __nv_bfloat16 Bs[BN * LDH];
    uint4* As4 = reinterpret_cast<uint4*>(As);
    uint4* Bs4 = reinterpret_cast<uint4*>(Bs);

    const int tid = threadIdx.x;
    const int warp = tid >> 5, lane = tid & 31;
    const int g = lane >> 2, tg = lane & 3;
    const int wm = (warp & 1) * 64;
    const int wn = (warp >> 1) * 32;

    // ---- loader mapping: thread -> (row = tid>>1, k-half = tid&1) ----
    const int lrow = tid >> 1;
    const int lk = (tid & 1) * 8;      // elems (bf16 for A, fp32 for B)
    const __nv_bfloat16* asrc = g_tnorm_h;  // safe dummy for OOB rows
    if (m0 + lrow < cnt) {
        int s = base + m0 + lrow;
        asrc = (IS_G1 ? (g_tnorm_h + (size_t)g_slot_token[s] * H_DIM)
                      : (g_act_h + (size_t)s * F_DIM)) + lk;
    }
    const float* Wb = W + (size_t)e * Nd * Kd;
    const float* bsrc = Wb + (size_t)(n0 + lrow) * Kd + lk;
    const int sIdx = lrow * 3 + (tid & 1);   // uint4 index (row stride 48B = 3 uint4)

    // ---- ldmatrix per-lane addresses (byte offsets; stride 48B/row) ----
    const int q = lane >> 3, qr = lane & 7;
    const uint32_t aFrag = (uint32_t)__cvta_generic_to_shared(As)
        + (uint32_t)((wm + (q & 1) * 8 + qr) * 48 + (q >> 1) * 16);
    const uint32_t bFrag = (uint32_t)__cvta_generic_to_shared(Bs)
        + (uint32_t)((wn + (q >> 1) * 8 + qr) * 48 + (q & 1) * 16);

    float acc[4][4][4];
#pragma unroll
    for (int mi = 0; mi < 4; mi++)
#pragma unroll
        for (int ni = 0; ni < 4; ni++)
#pragma unroll
            for (int z = 0; z < 4; z++) acc[mi][ni][z] = 0.f;

    // prologue loads
    uint4 aReg = *(const uint4*)(asrc);
    float4 bR0 = *(const float4*)(bsrc);
    float4 bR1 = *(const float4*)(bsrc + 4);

    const int NIT = Kd / BK;  // 64
#pragma unroll 1
    for (int it = 0; it < NIT; it++) {
        if (it) __syncthreads();
        // store staged tile (convert B fp32 -> bf16)
        As4[sIdx] = aReg;
        uint4 bp;
        bp.x = packbf(bR0.x, bR0.y);
        bp.y = packbf(bR0.z, bR0.w);
        bp.z = packbf(bR1.x, bR1.y);
        bp.w = packbf(bR1.z, bR1.w);
        Bs4[sIdx] = bp;
        __syncthreads();
        // prefetch next tile into registers (covered by compute below)
        if (it + 1 < NIT) {
            int k1 = (it + 1) * BK;
            aReg = *(const uint4*)(asrc + k1);
            bR0 = *(const float4*)(bsrc + k1);
            bR1 = *(const float4*)(bsrc + k1 + 4);
        }
        // fragments + MMA (one k16 step)
        uint32_t a[4][4], bq[2][4];
#pragma unroll
        for (int mi = 0; mi < 4; mi++) ldsm4(a[mi], aFrag + (uint32_t)(mi * 768));
#pragma unroll
        for (int p = 0; p < 2; p++) ldsm4(bq[p], bFrag + (uint32_t)(p * 768));
#pragma unroll
        for (int mi = 0; mi < 4; mi++) {
#pragma unroll
            for (int p = 0; p < 2; p++) {
                mma_bf16(acc[mi][2 * p + 0], a[mi], bq[p][0], bq[p][1]);
                mma_bf16(acc[mi][2 * p + 1], a[mi], bq[p][2], bq[p][3]);
            }
        }
    }

    // ---- epilogue (acc layout identical to tf32 version) ----
#pragma unroll
    for (int mi = 0; mi < 4; mi++) {
#pragma unroll
        for (int h2 = 0; h2 < 2; h2++) {
            int r = m0 + wm + mi * 16 + g + h2 * 8;
            if (r >= cnt) continue;
            int slot = base + r;
            float wsl = IS_G1 ? g_slot_weight[slot] : 0.f;
#pragma unroll
            for (int ni = 0; ni < 4; ni++) {
                int ceven = n0 + wn + ni * 8 + 2 * tg;
                float v0 = acc[mi][ni][h2 * 2 + 0];
                float v1 = acc[mi][ni][h2 * 2 + 1];
                if (IS_G1) {
                    const float2 bb = *(const float2*)(bias + (size_t)e * TWO_F + ceven);
                    float glu = fminf(v0 + bb.x, LIMIT);
                    float lin = fminf(fmaxf(v1 + bb.y, -LIMIT), LIMIT);
                    float act = glu * (1.f / (1.f + __expf(-ALPHA * glu))) * (lin + 1.f);
                    g_act_h[(size_t)slot * F_DIM + (ceven >> 1)] =
                        __float2bfloat16_rn(wsl * act);
                } else {
                    *(float2*)(g_y + (size_t)slot * H_DIM + ceven) = make_float2(v0, v1);
                }
            }
        }
    }
}

// ------------------- kernel 5: combine + residual + b2 -------------------
__global__ void k_combine(const float* __restrict__ x, const float* __restrict__ b2,
                          float* __restrict__ out) {
    int t = blockIdx.x, tid = threadIdx.x;
    int s0 = g_token_slot[t * 4 + 0], s1 = g_token_slot[t * 4 + 1];
    int s2 = g_token_slot[t * 4 + 2], s3 = g_token_slot[t * 4 + 3];
    int e0 = g_expert_ids[t * 4 + 0], e1 = g_expert_ids[t * 4 + 1];
    int e2 = g_expert_ids[t * 4 + 2], e3 = g_expert_ids[t * 4 + 3];
    float w0 = g_weights[t * 4 + 0], w1v = g_weights[t * 4 + 1];
    float w2v = g_weights[t * 4 + 2], w3 = g_weights[t * 4 + 3];
    for (int i = tid; i < H_DIM; i += 256) {
        float v = x[(size_t)t * H_DIM + i];
        v += g_y[(size_t)s0 * H_DIM + i] + w0 * b2[(size_t)e0 * H_DIM + i];
        v += g_y[(size_t)s1 * H_DIM + i] + w1v * b2[(size_t)e1 * H_DIM + i];
        v += g_y[(size_t)s2 * H_DIM + i] + w2v * b2[(size_t)e2 * H_DIM + i];
        v += g_y[(size_t)s3 * H_DIM + i] + w3 * b2[(size_t)e3 * H_DIM + i];
        out[(size_t)t * H_DIM + i] = v;
    }
}

// ------------------- launcher -------------------
extern "C" void kernel_launch(void* const* d_in, const int* in_sizes, int n_in,
                              void* d_out, int out_size) {
    const float* x = (const float*)d_in[0];
    const float* norm_scale = (const float*)d_in[1];
    const float* gate_w = (const float*)d_in[2];
    const float* gate_b = (const float*)d_in[3];
    const float* w1 = (const float*)d_in[4];
    const float* b1 = (const float*)d_in[5];
    const float* w2 = (const float*)d_in[6];
    const float* b2 = (const float*)d_in[7];
    float* out = (float*)d_out;

    k_zero<<<1, 32>>>();
    k_gate<<<T_TOK, 256>>>(x, norm_scale, gate_w, gate_b);
    k_scatter<<<1, 1024>>>();
    dim3 grid1(TWO_F / BN, T_TOK / BM, NE); // (16, 8, 32)
    k_gemm<1><<<grid1, 256>>>(w1, b1);
    dim3 grid2(H_DIM / BN, T_TOK / BM, NE); // (8, 8, 32)
    k_gemm<0><<<grid2, 256>>>(w2, nullptr);
    k_combine<<<T_TOK, 256>>>(x, b2, out);
}

// round 12
// speedup vs baseline: 2.0123x; 1.3241x over previous
// R12: tcgen05 is ILLEGAL under harness compile (PTX lowered to sm_103 family
// target, no 'a' features) — optimize the validated bf16 HMMA path instead.
// vs R10: BK 16->32 (2 k16 steps/iter), double-buffered smem (1 sync/iter),
// A via cp.async + B reg-staged, both overlapped with MMA. 80B rows: ldsm
// conflict-free. ~126 regs, 40KB smem, 2 CTAs/SM.
#include <cuda_runtime.h>
#include <cuda_bf16.h>
#include <cstdint>

#define T_TOK 1024
#define H_DIM 1024
#define NE 32
#define TOPK 4
#define F_DIM 1024
#define TWO_F 2048
#define LIMIT 7.0f
#define ALPHA 1.702f
#define EPS 1e-5f

#define BM 128
#define BN 128
#define BK 32
#define ROWE 40            // bf16 elems per smem row (80B stride)
#define STG_E (128 * ROWE) // elems per stage
#define STG_B (STG_E * 2)  // bytes per stage

// ------------------- scratch -------------------
__device__ __nv_bfloat16 g_tnorm_h[T_TOK * H_DIM];
__device__ int   g_counts[NE];
__device__ int   g_bases[NE];
__device__ int   g_expert_ids[T_TOK * TOPK];
__device__ float g_weights[T_TOK * TOPK];
__device__ int   g_slot_token[T_TOK * TOPK];
__device__ float g_slot_weight[T_TOK * TOPK];
__device__ int   g_token_slot[T_TOK * TOPK];
__device__ __nv_bfloat16 g_act_h[(size_t)T_TOK * TOPK * F_DIM];
__device__ float g_y[(size_t)T_TOK * TOPK * H_DIM];

// ------------------- helpers -------------------
__device__ __forceinline__ void mma_bf16(float (&d)[4], const uint32_t (&a)[4],
                                         uint32_t b0, uint32_t b1) {
    asm volatile(
        "mma.sync.aligned.m16n8k16.row.col.f32.bf16.bf16.f32 "
        "{%0,%1,%2,%3}, {%4,%5,%6,%7}, {%8,%9}, {%0,%1,%2,%3};\n"
        : "+f"(d[0]), "+f"(d[1]), "+f"(d[2]), "+f"(d[3])
        : "r"(a[0]), "r"(a[1]), "r"(a[2]), "r"(a[3]), "r"(b0), "r"(b1));
}
__device__ __forceinline__ void ldsm4(uint32_t (&r)[4], uint32_t addr) {
    asm volatile("ldmatrix.sync.aligned.m8n8.x4.shared.b16 {%0,%1,%2,%3}, [%4];"
                 : "=r"(r[0]), "=r"(r[1]), "=r"(r[2]), "=r"(r[3]) : "r"(addr));
}
__device__ __forceinline__ uint32_t packbf(float lo, float hi) {
    uint32_t r;
    asm("cvt.rn.bf16x2.f32 %0, %1, %2;" : "=r"(r) : "f"(hi), "f"(lo));
    return r;
}
__device__ __forceinline__ void cp16(uint32_t dst, const void* src, uint32_t sz) {
    asm volatile("cp.async.ca.shared.global [%0], [%1], 16, %2;\n"
                 ::"r"(dst), "l"(src), "r"(sz));
}
__device__ __forceinline__ void cp_commit() { asm volatile("cp.async.commit_group;\n"); }
__device__ __forceinline__ void cp_wait0() { asm volatile("cp.async.wait_group 0;\n"); }

// ------------------- kernel 0 -------------------
__global__ void k_zero() {
    if (threadIdx.x < NE) g_counts[threadIdx.x] = 0;
}

// ------------------- kernel 1: rmsnorm + gate + top4 + softmax ----------------
__global__ void k_gate(const float* __restrict__ x, const float* __restrict__ scale,
                       const float* __restrict__ gw, const float* __restrict__ gb) {
    int t = blockIdx.x;
    int tid = threadIdx.x;
    __shared__ float sh[H_DIM];
    __shared__ float red[8];
    __shared__ float logits[NE];
    const float* xr = x + (size_t)t * H_DIM;

    float ss = 0.f;
    for (int i = tid; i < H_DIM; i += 256) { float v = xr[i]; ss += v * v; }
    for (int o = 16; o; o >>= 1) ss += __shfl_xor_sync(~0u, ss, o);
    int warp = tid >> 5, lane = tid & 31;
    if (!lane) red[warp] = ss;
    __syncthreads();
    if (tid < 8) {
        float s = red[tid];
        for (int o = 4; o; o >>= 1) s += __shfl_xor_sync(0xffu, s, o);
        if (!tid) red[0] = s;
    }
    __syncthreads();
    float inv = rsqrtf(red[0] * (1.0f / H_DIM) + EPS);
    for (int i = tid; i < H_DIM; i += 256) {
        float v = xr[i] * inv * scale[i];
        sh[i] = v;
        g_tnorm_h[(size_t)t * H_DIM + i] = __float2bfloat16_rn(v);
    }
    __syncthreads();
    for (int e = warp; e < NE; e += 8) {
        const float* w = gw + (size_t)e * H_DIM;
        float s = 0.f;
        for (int i = lane; i < H_DIM; i += 32) s += sh[i] * w[i];
        for (int o = 16; o; o >>= 1) s += __shfl_xor_sync(~0u, s, o);
        if (!lane) logits[e] = s + gb[e];
    }
    __syncthreads();
    if (tid == 0) {
        unsigned used = 0;
        float v[TOPK]; int ix[TOPK];
        for (int k = 0; k < TOPK; k++) {
            float best = -3.4e38f; int bi = 0;
            for (int e2 = 0; e2 < NE; e2++)
                if (!((used >> e2) & 1u) && logits[e2] > best) { best = logits[e2]; bi = e2; }
            used |= 1u << bi; v[k] = best; ix[k] = bi;
        }
        float mx = v[0], sum = 0.f, w4[TOPK];
        for (int k = 0; k < TOPK; k++) { w4[k] = __expf(v[k] - mx); sum += w4[k]; }
        float rs = 1.f / sum;
        for (int k = 0; k < TOPK; k++) {
            g_expert_ids[t * TOPK + k] = ix[k];
            g_weights[t * TOPK + k] = w4[k] * rs;
            atomicAdd(&g_counts[ix[k]], 1);
        }
    }
}

// ------------------- kernel 2: deterministic scatter --------------------------
__global__ void k_scatter() {
    int e = threadIdx.x >> 5;
    int lane = threadIdx.x & 31;
    int base = 0;
    for (int i = 0; i < e; i++) base += g_counts[i];
    if (!lane) g_bases[e] = base;
    int running = 0;
    for (int j0 = 0; j0 < T_TOK * TOPK; j0 += 32) {
        int j = j0 + lane;
        int ee = g_expert_ids[j];
        unsigned m = __ballot_sync(~0u, ee == e);
        if (ee == e) {
            int slot = base + running + __popc(m & ((1u << lane) - 1u));
            g_slot_token[slot] = j >> 2;
            g_slot_weight[slot] = g_weights[j];
            g_token_slot[j] = slot;
        }
        running += __popc(m);
    }
}

// ------------------- kernel 3/4: bf16 HMMA GEMM, double-buffered --------------
// IS_G1=1: act_h[slot,f] = bf16(w_slot * swiglu(tnorm_h[token] @ w1[e]^T + b1[e]))
// IS_G1=0: y[slot,h]     = act_h[slot,:] @ w2[e]^T
template <int IS_G1>
__global__ __launch_bounds__(256, 2) void k_gemm(const float* __restrict__ W,
                                                 const float* __restrict__ bias) {
    const int Kd = 1024;
    const int Nd = IS_G1 ? TWO_F : H_DIM;
    const int e = blockIdx.z;
    const int cnt = g_counts[e];
    const int m0 = blockIdx.y * BM;
    if (m0 >= cnt) return;
    const int base = g_bases[e];
    const int n0 = blockIdx.x * BN;

    __shared__ __align__(16) __nv_bfloat16 As[2][STG_E];
    __shared__ __align__(16) __nv_bfloat16 Bs[2][STG_E];

    const int tid = threadIdx.x;
    const int warp = tid >> 5, lane = tid & 31;
    const int g = lane >> 2, tg = lane & 3;
    const int wm = (warp & 1) * 64;
    const int wn = (warp >> 1) * 32;

    // ---- loader mapping: 512 16B dst chunks each (A,B); 2 per thread ----
    // chunk c: row = c>>2, u = c&3 (16B unit = 8 elems)
    const float* Wb = W + (size_t)e * Nd * Kd;
    const __nv_bfloat16* asrc[2]; uint32_t asz[2], aDst[2];
    const float* bsrc[2]; uint32_t bDst[2];
#pragma unroll
    for (int j = 0; j < 2; j++) {
        int c = tid + 256 * j;
        int row = c >> 2, u = c & 3;
        if (m0 + row < cnt) {
            int s = base + m0 + row;
            asrc[j] = (IS_G1 ? (g_tnorm_h + (size_t)g_slot_token[s] * H_DIM)
                             : (g_act_h + (size_t)s * F_DIM)) + u * 8;
            asz[j] = 16;
        } else {
            asrc[j] = g_tnorm_h; asz[j] = 0;
        }
        aDst[j] = (uint32_t)__cvta_generic_to_shared(As)
                  + (uint32_t)(row * 80 + u * 16);
        bsrc[j] = Wb + (size_t)(n0 + row) * Kd + u * 8;
        bDst[j] = (uint32_t)__cvta_generic_to_shared(Bs)
                  + (uint32_t)(row * 80 + u * 16);
    }

    // ---- ldmatrix per-lane fragment bases (stage 0) ----
    const int q = lane >> 3, qr = lane & 7;
    const uint32_t aFrag = (uint32_t)__cvta_generic_to_shared(As)
        + (uint32_t)((wm + (q & 1) * 8 + qr) * 80 + (q >> 1) * 16);
    const uint32_t bFrag = (uint32_t)__cvta_generic_to_shared(Bs)
        + (uint32_t)((wn + (q >> 1) * 8 + qr) * 80 + (q & 1) * 16);

    float acc[4][4][4];
#pragma unroll
    for (int mi = 0; mi < 4; mi++)
#pragma unroll
        for (int ni = 0; ni < 4; ni++)
#pragma unroll
            for (int z = 0; z < 4; z++) acc[mi][ni][z] = 0.f;

    // ---- prologue: A stage0 via cp.async; B k0 into regs ----
#pragma unroll
    for (int j = 0; j < 2; j++) cp16(aDst[j], asrc[j], asz[j]);
    cp_commit();
    float4 bR[2][2];
#pragma unroll
    for (int j = 0; j < 2; j++) {
        bR[j][0] = *(const float4*)(bsrc[j]);
        bR[j][1] = *(const float4*)(bsrc[j] + 4);
    }

    const int NIT = Kd / BK;  // 32
#pragma unroll 1
    for (int it = 0; it < NIT; it++) {
        const uint32_t s = (uint32_t)(it & 1);
        // STS B (staged regs) into stage s
#pragma unroll
        for (int j = 0; j < 2; j++) {
            uint4 p;
            p.x = packbf(bR[j][0].x, bR[j][0].y);
            p.y = packbf(bR[j][0].z, bR[j][0].w);
            p.z = packbf(bR[j][1].x, bR[j][1].y);
            p.w = packbf(bR[j][1].z, bR[j][1].w);
            asm volatile("st.shared.v4.b32 [%0], {%1,%2,%3,%4};"
                         ::"r"(bDst[j] + s * STG_B), "r"(p.x), "r"(p.y), "r"(p.z), "r"(p.w));
        }
        cp_wait0();          // A stage s complete
        __syncthreads();     // tile (s) fully visible; stage s^1 free
        if (it + 1 < NIT) {  // prefetch next tile (overlapped with MMAs below)
            const int k1 = (it + 1) * BK;
#pragma unroll
            for (int j = 0; j < 2; j++) cp16(aDst[j] + (s ^ 1) * STG_B, asrc[j] + k1, asz[j]);
            cp_commit();
#pragma unroll
            for (int j = 0; j < 2; j++) {
                bR[j][0] = *(const float4*)(bsrc[j] + k1);
                bR[j][1] = *(const float4*)(bsrc[j] + k1 + 4);
            }
        }
        const uint32_t aS = aFrag + s * STG_B;
        const uint32_t bS = bFrag + s * STG_B;
#pragma unroll
        for (int kk = 0; kk < 2; kk++) {          // two k16 steps (byte off kk*32)
            uint32_t a[4][4], bq[2][4];
#pragma unroll
            for (int mi = 0; mi < 4; mi++)
                ldsm4(a[mi], aS + (uint32_t)(mi * 16 * 80 + kk * 32));
#pragma unroll
            for (int p = 0; p < 2; p++)
                ldsm4(bq[p], bS + (uint32_t)(p * 16 * 80 + kk * 32));
#pragma unroll
            for (int mi = 0; mi < 4; mi++) {
#pragma unroll
                for (int p = 0; p < 2; p++) {
                    mma_bf16(acc[mi][2 * p + 0], a[mi], bq[p][0], bq[p][1]);
                    mma_bf16(acc[mi][2 * p + 1], a[mi], bq[p][2], bq[p][3]);
                }
            }
        }
    }

    // ---- epilogue (acc layout identical to R10) ----
#pragma unroll
    for (int mi = 0; mi < 4; mi++) {
#pragma unroll
        for (int h2 = 0; h2 < 2; h2++) {
            int r = m0 + wm + mi * 16 + g + h2 * 8;
            if (r >= cnt) continue;
            int slot = base + r;
            float wsl = IS_G1 ? g_slot_weight[slot] : 0.f;
#pragma unroll
            for (int ni = 0; ni < 4; ni++) {
                int ceven = n0 + wn + ni * 8 + 2 * tg;
                float v0 = acc[mi][ni][h2 * 2 + 0];
                float v1 = acc[mi][ni][h2 * 2 + 1];
                if (IS_G1) {
                    const float2 bb = *(const float2*)(bias + (size_t)e * TWO_F + ceven);
                    float glu = fminf(v0 + bb.x, LIMIT);
                    float lin = fminf(fmaxf(v1 + bb.y, -LIMIT), LIMIT);
                    float act = glu * (1.f / (1.f + __expf(-ALPHA * glu))) * (lin + 1.f);
                    g_act_h[(size_t)slot * F_DIM + (ceven >> 1)] =
                        __float2bfloat16_rn(wsl * act);
                } else {
                    *(float2*)(g_y + (size_t)slot * H_DIM + ceven) = make_float2(v0, v1);
                }
            }
        }
    }
}

// ------------------- kernel 5: combine + residual + b2 -------------------
__global__ void k_combine(const float* __restrict__ x, const float* __restrict__ b2,
                          float* __restrict__ out) {
    int t = blockIdx.x, tid = threadIdx.x;
    int s0 = g_token_slot[t * 4 + 0], s1 = g_token_slot[t * 4 + 1];
    int s2 = g_token_slot[t * 4 + 2], s3 = g_token_slot[t * 4 + 3];
    int e0 = g_expert_ids[t * 4 + 0], e1 = g_expert_ids[t * 4 + 1];
    int e2 = g_expert_ids[t * 4 + 2], e3 = g_expert_ids[t * 4 + 3];
    float w0 = g_weights[t * 4 + 0], w1v = g_weights[t * 4 + 1];
    float w2v = g_weights[t * 4 + 2], w3 = g_weights[t * 4 + 3];
    for (int i = tid; i < H_DIM; i += 256) {
        float v = x[(size_t)t * H_DIM + i];
        v += g_y[(size_t)s0 * H_DIM + i] + w0 * b2[(size_t)e0 * H_DIM + i];
        v += g_y[(size_t)s1 * H_DIM + i] + w1v * b2[(size_t)e1 * H_DIM + i];
        v += g_y[(size_t)s2 * H_DIM + i] + w2v * b2[(size_t)e2 * H_DIM + i];
        v += g_y[(size_t)s3 * H_DIM + i] + w3 * b2[(size_t)e3 * H_DIM + i];
        out[(size_t)t * H_DIM + i] = v;
    }
}

// ------------------- launcher -------------------
extern "C" void kernel_launch(void* const* d_in, const int* in_sizes, int n_in,
                              void* d_out, int out_size) {
    const float* x = (const float*)d_in[0];
    const float* norm_scale = (const float*)d_in[1];
    const float* gate_w = (const float*)d_in[2];
    const float* gate_b = (const float*)d_in[3];
    const float* w1 = (const float*)d_in[4];
    const float* b1 = (const float*)d_in[5];
    const float* w2 = (const float*)d_in[6];
    const float* b2 = (const float*)d_in[7];
    float* out = (float*)d_out;

    k_zero<<<1, 32>>>();
    k_gate<<<T_TOK, 256>>>(x, norm_scale, gate_w, gate_b);
    k_scatter<<<1, 1024>>>();
    dim3 grid1(TWO_F / BN, T_TOK / BM, NE); // (16, 8, 32)
    k_gemm<1><<<grid1, 256>>>(w1, b1);
    dim3 grid2(H_DIM / BN, T_TOK / BM, NE); // (8, 8, 32)
    k_gemm<0><<<grid2, 256>>>(w2, nullptr);
    k_combine<<<T_TOK, 256>>>(x, b2, out);
}